// round 1
// baseline (speedup 1.0000x reference)
#include <cuda_runtime.h>
#include <cuda_bf16.h>

#define TWO_PI_F     6.2831853071795864769f
#define INV_TWO_PI_F 0.15915494309189533577f

// diff_round(x) = x - sin(2*pi*x)/(2*pi)
__device__ __forceinline__ float dr(float x) {
    return fmaf(-__sinf(x * TWO_PI_F), INV_TWO_PI_F, x);
}
// harder_diff_round = dr(dr(dr(x)))
__device__ __forceinline__ float hdr(float x) { return dr(dr(dr(x))); }

// differentiable_eq with b already harder_diff_rounded (precomputed per area):
// eq = hdr( a'*b + (1-a')*(1-b) ) = hdr( 1 - a' - b + 2*a'*b ), a' = hdr(a)
__device__ __forceinline__ float deq(float a, float bh) {
    float ah = hdr(a);
    float t = fmaf(2.0f * ah, bh, 1.0f - ah - bh);
    return hdr(t);
}

// full mask value for one pixel given 4 mask channels + 4 pre-hdr'd id values
__device__ __forceinline__ float mask_m(float4 mv, float i0, float i1, float i2, float i3) {
    float e0 = deq(mv.x, i0);
    float e1 = deq(mv.y, i1);
    float e2 = deq(mv.z, i2);
    float e3 = deq(mv.w, i3);
    float pa = dr(e0) * dr(e1);   // differentiable_and(e0, e1)
    float pb = dr(e2) * dr(e3);   // differentiable_and(e2, e3)
    return dr(pa) * dr(pb);       // differentiable_and(pa, pb)
}

// One block per (batch, area): 256 threads = 16x16 pixels.
// Computes both out_image and out_image_alt in a single pass.
__global__ __launch_bounds__(256, 8)
void deconv_masks_kernel(const float*  __restrict__ img,      // [B*N*256]
                         const float4* __restrict__ mask0,    // [B*N*256] float4
                         const float4* __restrict__ mask1,    // [B*N*256] float4
                         const float*  __restrict__ mid,      // [B*N*4]
                         float*        __restrict__ out,      // [2 * B*N*256]
                         int n_pix_total)                     // B*N*256
{
    __shared__ float sid[4];
    __shared__ float4 warp_part[8];
    __shared__ float4 totals;

    const int area = blockIdx.x;
    const int p    = threadIdx.x;          // 0..255
    const int lane = p & 31;
    const int wrp  = p >> 5;

    // Precompute hdr(initial_mask_id) once per area (shared by both mask tensors)
    if (p < 4) sid[p] = hdr(mid[(size_t)area * 4 + p]);
    __syncthreads();

    const float i0 = sid[0], i1 = sid[1], i2 = sid[2], i3 = sid[3];

    const size_t pix = (size_t)area * 256 + p;
    const float  iv  = img[pix];
    const float4 m0v = mask0[pix];
    const float4 m1v = mask1[pix];

    const float m0 = mask_m(m0v, i0, i1, i2, i3);
    const float m1 = mask_m(m1v, i0, i1, i2, i3);

    // Packed reduction: (num0, den0, num1, den1)
    float4 acc = make_float4(m0 * iv, m0, m1 * iv, m1);

    #pragma unroll
    for (int off = 16; off > 0; off >>= 1) {
        acc.x += __shfl_down_sync(0xffffffffu, acc.x, off);
        acc.y += __shfl_down_sync(0xffffffffu, acc.y, off);
        acc.z += __shfl_down_sync(0xffffffffu, acc.z, off);
        acc.w += __shfl_down_sync(0xffffffffu, acc.w, off);
    }
    if (lane == 0) warp_part[wrp] = acc;
    __syncthreads();

    if (wrp == 0) {
        float4 a = (lane < 8) ? warp_part[lane] : make_float4(0.f, 0.f, 0.f, 0.f);
        #pragma unroll
        for (int off = 4; off > 0; off >>= 1) {
            a.x += __shfl_down_sync(0xffffffffu, a.x, off);
            a.y += __shfl_down_sync(0xffffffffu, a.y, off);
            a.z += __shfl_down_sync(0xffffffffu, a.z, off);
            a.w += __shfl_down_sync(0xffffffffu, a.w, off);
        }
        if (lane == 0) totals = a;
    }
    __syncthreads();

    const float mean0 = totals.x / totals.y;
    const float mean1 = totals.z / totals.w;

    out[pix]                       = m0 * mean0;   // out_image
    out[pix + (size_t)n_pix_total] = m1 * mean1;   // out_image_alt
}

extern "C" void kernel_launch(void* const* d_in, const int* in_sizes, int n_in,
                              void* d_out, int out_size) {
    // metadata order:
    // 0: resized_image       [B,N,16,16,1] f32
    // 1: mask_combined       [B,N,16,16,4] f32
    // 2: mask_combined_alt   [B,N,16,16,4] f32
    // 3: initial_mask_id     [B,N,4]       f32
    // 4: mask_new_bi_channel (unused)
    // 5: mask_index          (unused)
    const float*  img   = (const float*) d_in[0];
    const float4* mask0 = (const float4*)d_in[1];
    const float4* mask1 = (const float4*)d_in[2];
    const float*  mid   = (const float*) d_in[3];
    float*        out   = (float*)d_out;

    const int n_pix = in_sizes[0];        // B*N*256 = 4,194,304
    const int areas = n_pix / 256;        // 16,384

    deconv_masks_kernel<<<areas, 256>>>(img, mask0, mask1, mid, out, n_pix);
}

// round 2
// speedup vs baseline: 1.0252x; 1.0252x over previous
#include <cuda_runtime.h>
#include <cuda_bf16.h>

#define TWO_PI_F     6.2831853071795864769f
#define INV_TWO_PI_F 0.15915494309189533577f

typedef unsigned long long u64;

// ---------- packed f32x2 primitives (Blackwell) ----------
__device__ __forceinline__ u64 pk2(float lo, float hi) {
    u64 r; asm("mov.b64 %0, {%1,%2};" : "=l"(r) : "f"(lo), "f"(hi)); return r;
}
__device__ __forceinline__ void upk2(u64 v, float& lo, float& hi) {
    asm("mov.b64 {%0,%1}, %2;" : "=f"(lo), "=f"(hi) : "l"(v));
}
__device__ __forceinline__ u64 f2add(u64 a, u64 b) {
    u64 r; asm("add.rn.f32x2 %0,%1,%2;" : "=l"(r) : "l"(a), "l"(b)); return r;
}
__device__ __forceinline__ u64 f2mul(u64 a, u64 b) {
    u64 r; asm("mul.rn.f32x2 %0,%1,%2;" : "=l"(r) : "l"(a), "l"(b)); return r;
}
__device__ __forceinline__ u64 f2fma(u64 a, u64 b, u64 c) {
    u64 r; asm("fma.rn.f32x2 %0,%1,%2,%3;" : "=l"(r) : "l"(a), "l"(b), "l"(c)); return r;
}

// ---------- scalar dr (used only for the per-area id precompute) ----------
__device__ __forceinline__ float dr_s(float x) {
    return fmaf(-__sinf(x * TWO_PI_F), INV_TWO_PI_F, x);
}
__device__ __forceinline__ float hdr_s(float x) { return dr_s(dr_s(dr_s(x))); }

// ---------- packed dr via MUFU.SIN (pipe: MUFU + a little FMA) ----------
__device__ __forceinline__ u64 dr_mufu2(u64 x) {
    const u64 K2PI  = pk2(TWO_PI_F, TWO_PI_F);
    const u64 KMI2P = pk2(-INV_TWO_PI_F, -INV_TWO_PI_F);
    u64 y = f2mul(x, K2PI);
    float ylo, yhi; upk2(y, ylo, yhi);
    u64 s = pk2(__sinf(ylo), __sinf(yhi));
    return f2fma(s, KMI2P, x);   // x - sin(2pi x)/(2pi)
}
__device__ __forceinline__ u64 hdr_mufu2(u64 x) { return dr_mufu2(dr_mufu2(dr_mufu2(x))); }

// ---------- packed dr via polynomial (pipe: FMA only) ----------
// Valid for x in ~[-0.1, 1.1]. u = x-0.5, sin(2pi x) = -sin(2pi u),
// dr(x) = x + u*G(u^2), u*G(u^2) ~= sin(2pi u)/(2pi), Taylor deg 13.
__device__ __forceinline__ u64 dr_poly2(u64 x) {
    const u64 KMH = pk2(-0.5f, -0.5f);
    const u64 G6  = pk2( 0.6079630f,      0.6079630f);
    const u64 G5  = pk2(-2.4023850f,     -2.4023850f);
    const u64 G4  = pk2( 6.6938510f,      6.6938510f);
    const u64 G3  = pk2(-12.2081160f,    -12.2081160f);
    const u64 G2  = pk2( 12.98787880f,    12.98787880f);
    const u64 G1  = pk2(-6.57973627f,    -6.57973627f);
    const u64 G0  = pk2( 1.0f,            1.0f);
    u64 u = f2add(x, KMH);
    u64 e = f2mul(u, u);
    u64 p = f2fma(e, G6, G5);
    p = f2fma(p, e, G4);
    p = f2fma(p, e, G3);
    p = f2fma(p, e, G2);
    p = f2fma(p, e, G1);
    p = f2fma(p, e, G0);
    return f2fma(p, u, x);       // x + u*G(u^2)
}
__device__ __forceinline__ u64 hdr_poly2(u64 x) { return dr_poly2(dr_poly2(dr_poly2(x))); }

// t = (1-a)(1-b) + a*b = 1 - a - b + 2ab   (packed)
__device__ __forceinline__ u64 eq_combine2(u64 ah, u64 bh) {
    const u64 KONE  = pk2(1.0f, 1.0f);
    const u64 KMONE = pk2(-1.0f, -1.0f);
    const u64 KTWO  = pk2(2.0f, 2.0f);
    u64 pm = f2mul(ah, bh);
    u64 q  = f2add(ah, bh);
    u64 r  = f2fma(q, KMONE, KONE);   // 1 - a - b
    return f2fma(pm, KTWO, r);        // + 2ab
}

// One block per (batch, area): 256 threads = 16x16 pixels.
// mask0/mask1 computed together as f32x2 lanes.
__global__ __launch_bounds__(256, 4)
void deconv_masks_kernel(const float*  __restrict__ img,
                         const float4* __restrict__ mask0,
                         const float4* __restrict__ mask1,
                         const float*  __restrict__ mid,
                         float*        __restrict__ out,
                         int n_pix_total)
{
    __shared__ float sid[4];
    __shared__ float4 warp_part[8];
    __shared__ float4 totals;

    const int area = blockIdx.x;
    const int p    = threadIdx.x;
    const int lane = p & 31;
    const int wrp  = p >> 5;

    if (p < 4) sid[p] = hdr_s(mid[(size_t)area * 4 + p]);
    __syncthreads();

    const u64 b0 = pk2(sid[0], sid[0]);
    const u64 b1 = pk2(sid[1], sid[1]);
    const u64 b2 = pk2(sid[2], sid[2]);
    const u64 b3 = pk2(sid[3], sid[3]);

    const size_t pix = (size_t)area * 256 + p;
    const float  iv  = img[pix];
    const float4 m0v = mask0[pix];
    const float4 m1v = mask1[pix];

    // Pack (mask0, mask1) per channel
    u64 a0 = pk2(m0v.x, m1v.x);
    u64 a1 = pk2(m0v.y, m1v.y);
    u64 a2 = pk2(m0v.z, m1v.z);
    u64 a3 = pk2(m0v.w, m1v.w);

    // hdr(a): 12 dr-pairs on the FMA pipe (polynomial)
    u64 ah0 = hdr_poly2(a0);
    u64 ah1 = hdr_poly2(a1);
    u64 ah2 = hdr_poly2(a2);
    u64 ah3 = hdr_poly2(a3);

    // hdr(t) + dr(e): 16 dr-pairs on the MUFU pipe
    u64 d0 = dr_mufu2(hdr_mufu2(eq_combine2(ah0, b0)));
    u64 d1 = dr_mufu2(hdr_mufu2(eq_combine2(ah1, b1)));
    u64 d2 = dr_mufu2(hdr_mufu2(eq_combine2(ah2, b2)));
    u64 d3 = dr_mufu2(hdr_mufu2(eq_combine2(ah3, b3)));

    // ANDs: dr(pa)*dr(pb) etc: 2 more MUFU pairs
    u64 pa = f2mul(d0, d1);
    u64 pb = f2mul(d2, d3);
    u64 mm = f2mul(dr_mufu2(pa), dr_mufu2(pb));

    float m0, m1; upk2(mm, m0, m1);

    // Packed reduction of (num0, den0, num1, den1)
    float4 acc = make_float4(m0 * iv, m0, m1 * iv, m1);

    #pragma unroll
    for (int off = 16; off > 0; off >>= 1) {
        acc.x += __shfl_down_sync(0xffffffffu, acc.x, off);
        acc.y += __shfl_down_sync(0xffffffffu, acc.y, off);
        acc.z += __shfl_down_sync(0xffffffffu, acc.z, off);
        acc.w += __shfl_down_sync(0xffffffffu, acc.w, off);
    }
    if (lane == 0) warp_part[wrp] = acc;
    __syncthreads();

    if (wrp == 0) {
        float4 a = (lane < 8) ? warp_part[lane] : make_float4(0.f, 0.f, 0.f, 0.f);
        #pragma unroll
        for (int off = 4; off > 0; off >>= 1) {
            a.x += __shfl_down_sync(0xffffffffu, a.x, off);
            a.y += __shfl_down_sync(0xffffffffu, a.y, off);
            a.z += __shfl_down_sync(0xffffffffu, a.z, off);
            a.w += __shfl_down_sync(0xffffffffu, a.w, off);
        }
        if (lane == 0) totals = a;
    }
    __syncthreads();

    const float mean0 = totals.x / totals.y;
    const float mean1 = totals.z / totals.w;

    out[pix]                       = m0 * mean0;
    out[pix + (size_t)n_pix_total] = m1 * mean1;
}

extern "C" void kernel_launch(void* const* d_in, const int* in_sizes, int n_in,
                              void* d_out, int out_size) {
    const float*  img   = (const float*) d_in[0];
    const float4* mask0 = (const float4*)d_in[1];
    const float4* mask1 = (const float4*)d_in[2];
    const float*  mid   = (const float*) d_in[3];
    float*        out   = (float*)d_out;

    const int n_pix = in_sizes[0];
    const int areas = n_pix / 256;

    deconv_masks_kernel<<<areas, 256>>>(img, mask0, mask1, mid, out, n_pix);
}

// round 3
// speedup vs baseline: 1.2300x; 1.1998x over previous
#include <cuda_runtime.h>
#include <cuda_bf16.h>

#define TWO_PI_F     6.2831853071795864769f
#define INV_TWO_PI_F 0.15915494309189533577f

typedef unsigned long long u64;

// ---------- packed f32x2 primitives (Blackwell) ----------
__device__ __forceinline__ u64 pk2(float lo, float hi) {
    u64 r; asm("mov.b64 %0, {%1,%2};" : "=l"(r) : "f"(lo), "f"(hi)); return r;
}
__device__ __forceinline__ void upk2(u64 v, float& lo, float& hi) {
    asm("mov.b64 {%0,%1}, %2;" : "=f"(lo), "=f"(hi) : "l"(v));
}
__device__ __forceinline__ u64 f2add(u64 a, u64 b) {
    u64 r; asm("add.rn.f32x2 %0,%1,%2;" : "=l"(r) : "l"(a), "l"(b)); return r;
}
__device__ __forceinline__ u64 f2mul(u64 a, u64 b) {
    u64 r; asm("mul.rn.f32x2 %0,%1,%2;" : "=l"(r) : "l"(a), "l"(b)); return r;
}
__device__ __forceinline__ u64 f2fma(u64 a, u64 b, u64 c) {
    u64 r; asm("fma.rn.f32x2 %0,%1,%2,%3;" : "=l"(r) : "l"(a), "l"(b), "l"(c)); return r;
}

// ---------- scalar dr (per-area id precompute only) ----------
__device__ __forceinline__ float dr_s(float x) {
    return fmaf(-__sinf(x * TWO_PI_F), INV_TWO_PI_F, x);
}
__device__ __forceinline__ float hdr_s(float x) { return dr_s(dr_s(dr_s(x))); }

// ---------- packed dr via MUFU.SIN ----------
__device__ __forceinline__ u64 dr_mufu2(u64 x) {
    const u64 K2PI  = pk2(TWO_PI_F, TWO_PI_F);
    const u64 KMI2P = pk2(-INV_TWO_PI_F, -INV_TWO_PI_F);
    u64 y = f2mul(x, K2PI);
    float ylo, yhi; upk2(y, ylo, yhi);
    u64 s = pk2(__sinf(ylo), __sinf(yhi));
    return f2fma(s, KMI2P, x);
}
__device__ __forceinline__ u64 hdr_mufu2(u64 x) { return dr_mufu2(dr_mufu2(dr_mufu2(x))); }

// ---------- packed dr via polynomial (FMA pipe only) ----------
// u = x-0.5 in [-0.5,0.5]; dr(x) = x + u*G(u^2), Taylor deg 13 of sin(2pi u)/(2pi)
__device__ __forceinline__ u64 dr_poly2(u64 x) {
    const u64 KMH = pk2(-0.5f, -0.5f);
    const u64 G6  = pk2( 0.6079630f,      0.6079630f);
    const u64 G5  = pk2(-2.4023850f,     -2.4023850f);
    const u64 G4  = pk2( 6.6938510f,      6.6938510f);
    const u64 G3  = pk2(-12.2081160f,    -12.2081160f);
    const u64 G2  = pk2( 12.98787880f,    12.98787880f);
    const u64 G1  = pk2(-6.57973627f,    -6.57973627f);
    const u64 G0  = pk2( 1.0f,            1.0f);
    u64 u = f2add(x, KMH);
    u64 e = f2mul(u, u);
    u64 p = f2fma(e, G6, G5);
    p = f2fma(p, e, G4);
    p = f2fma(p, e, G3);
    p = f2fma(p, e, G2);
    p = f2fma(p, e, G1);
    p = f2fma(p, e, G0);
    return f2fma(p, u, x);
}
__device__ __forceinline__ u64 hdr_poly2(u64 x) { return dr_poly2(dr_poly2(dr_poly2(x))); }

// t = 1 - a - b + 2ab (packed)
__device__ __forceinline__ u64 eq_combine2(u64 ah, u64 bh) {
    const u64 KONE  = pk2(1.0f, 1.0f);
    const u64 KMONE = pk2(-1.0f, -1.0f);
    const u64 KTWO  = pk2(2.0f, 2.0f);
    u64 pm = f2mul(ah, bh);
    u64 q  = f2add(ah, bh);
    u64 r  = f2fma(q, KMONE, KONE);
    return f2fma(pm, KTWO, r);
}

// full packed mask pair (m0,m1) for one pixel
__device__ __forceinline__ u64 mask_pair(float4 m0v, float4 m1v,
                                         u64 b0, u64 b1, u64 b2, u64 b3) {
    u64 a0 = pk2(m0v.x, m1v.x);
    u64 a1 = pk2(m0v.y, m1v.y);
    u64 a2 = pk2(m0v.z, m1v.z);
    u64 a3 = pk2(m0v.w, m1v.w);

    // hdr(a): FMA pipe (polynomial)
    u64 ah0 = hdr_poly2(a0);
    u64 ah1 = hdr_poly2(a1);
    u64 ah2 = hdr_poly2(a2);
    u64 ah3 = hdr_poly2(a3);

    // hdr(t) + dr(e): MUFU pipe
    u64 d0 = dr_mufu2(hdr_mufu2(eq_combine2(ah0, b0)));
    u64 d1 = dr_mufu2(hdr_mufu2(eq_combine2(ah1, b1)));
    u64 d2 = dr_mufu2(hdr_mufu2(eq_combine2(ah2, b2)));
    u64 d3 = dr_mufu2(hdr_mufu2(eq_combine2(ah3, b3)));

    u64 pa = f2mul(d0, d1);
    u64 pb = f2mul(d2, d3);
    return f2mul(dr_mufu2(pa), dr_mufu2(pb));
}

// One block per area: 128 threads, 2 pixels each (t and t+128) for ILP.
__global__ __launch_bounds__(128, 6)
void deconv_masks_kernel(const float*  __restrict__ img,
                         const float4* __restrict__ mask0,
                         const float4* __restrict__ mask1,
                         const float*  __restrict__ mid,
                         float*        __restrict__ out,
                         int n_pix_total)
{
    __shared__ float sid[4];
    __shared__ float4 warp_part[4];
    __shared__ float4 totals;

    const int area = blockIdx.x;
    const int t    = threadIdx.x;          // 0..127
    const int lane = t & 31;
    const int wrp  = t >> 5;

    if (t < 4) sid[t] = hdr_s(mid[(size_t)area * 4 + t]);
    __syncthreads();

    const u64 b0 = pk2(sid[0], sid[0]);
    const u64 b1 = pk2(sid[1], sid[1]);
    const u64 b2 = pk2(sid[2], sid[2]);
    const u64 b3 = pk2(sid[3], sid[3]);

    const size_t pixA = (size_t)area * 256 + t;
    const size_t pixB = pixA + 128;

    const float  ivA  = img[pixA];
    const float  ivB  = img[pixB];
    const float4 m0A  = mask0[pixA];
    const float4 m1A  = mask1[pixA];
    const float4 m0B  = mask0[pixB];
    const float4 m1B  = mask1[pixB];

    // two independent dependency chains (compiler interleaves)
    u64 mmA = mask_pair(m0A, m1A, b0, b1, b2, b3);
    u64 mmB = mask_pair(m0B, m1B, b0, b1, b2, b3);

    float m0a, m1a, m0b, m1b;
    upk2(mmA, m0a, m1a);
    upk2(mmB, m0b, m1b);

    // fold both pixels into one accumulator, then reduce over 128 threads
    float4 acc = make_float4(fmaf(m0a, ivA, m0b * ivB),
                             m0a + m0b,
                             fmaf(m1a, ivA, m1b * ivB),
                             m1a + m1b);

    #pragma unroll
    for (int off = 16; off > 0; off >>= 1) {
        acc.x += __shfl_down_sync(0xffffffffu, acc.x, off);
        acc.y += __shfl_down_sync(0xffffffffu, acc.y, off);
        acc.z += __shfl_down_sync(0xffffffffu, acc.z, off);
        acc.w += __shfl_down_sync(0xffffffffu, acc.w, off);
    }
    if (lane == 0) warp_part[wrp] = acc;
    __syncthreads();

    if (wrp == 0) {
        float4 a = (lane < 4) ? warp_part[lane] : make_float4(0.f, 0.f, 0.f, 0.f);
        #pragma unroll
        for (int off = 2; off > 0; off >>= 1) {
            a.x += __shfl_down_sync(0xffffffffu, a.x, off);
            a.y += __shfl_down_sync(0xffffffffu, a.y, off);
            a.z += __shfl_down_sync(0xffffffffu, a.z, off);
            a.w += __shfl_down_sync(0xffffffffu, a.w, off);
        }
        if (lane == 0) totals = a;
    }
    __syncthreads();

    const float mean0 = __fdividef(totals.x, totals.y);
    const float mean1 = __fdividef(totals.z, totals.w);

    out[pixA]                       = m0a * mean0;
    out[pixA + (size_t)n_pix_total] = m1a * mean1;
    out[pixB]                       = m0b * mean0;
    out[pixB + (size_t)n_pix_total] = m1b * mean1;
}

extern "C" void kernel_launch(void* const* d_in, const int* in_sizes, int n_in,
                              void* d_out, int out_size) {
    const float*  img   = (const float*) d_in[0];
    const float4* mask0 = (const float4*)d_in[1];
    const float4* mask1 = (const float4*)d_in[2];
    const float*  mid   = (const float*) d_in[3];
    float*        out   = (float*)d_out;

    const int n_pix = in_sizes[0];
    const int areas = n_pix / 256;

    deconv_masks_kernel<<<areas, 128>>>(img, mask0, mask1, mid, out, n_pix);
}

// round 4
// speedup vs baseline: 1.3868x; 1.1275x over previous
#include <cuda_runtime.h>
#include <cuda_bf16.h>

#define TWO_PI_F     6.2831853071795864769f
#define INV_TWO_PI_F 0.15915494309189533577f

typedef unsigned long long u64;

// ---------- packed f32x2 primitives (Blackwell) ----------
__device__ __forceinline__ u64 pk2(float lo, float hi) {
    u64 r; asm("mov.b64 %0, {%1,%2};" : "=l"(r) : "f"(lo), "f"(hi)); return r;
}
__device__ __forceinline__ void upk2(u64 v, float& lo, float& hi) {
    asm("mov.b64 {%0,%1}, %2;" : "=f"(lo), "=f"(hi) : "l"(v));
}
__device__ __forceinline__ u64 f2add(u64 a, u64 b) {
    u64 r; asm("add.rn.f32x2 %0,%1,%2;" : "=l"(r) : "l"(a), "l"(b)); return r;
}
__device__ __forceinline__ u64 f2mul(u64 a, u64 b) {
    u64 r; asm("mul.rn.f32x2 %0,%1,%2;" : "=l"(r) : "l"(a), "l"(b)); return r;
}
__device__ __forceinline__ u64 f2fma(u64 a, u64 b, u64 c) {
    u64 r; asm("fma.rn.f32x2 %0,%1,%2,%3;" : "=l"(r) : "l"(a), "l"(b), "l"(c)); return r;
}

// ---------- scalar dr (per-area id precompute only) ----------
__device__ __forceinline__ float dr_s(float x) {
    return fmaf(-__sinf(x * TWO_PI_F), INV_TWO_PI_F, x);
}
__device__ __forceinline__ float hdr_s(float x) { return dr_s(dr_s(dr_s(x))); }

// ---------- packed dr via MUFU.SIN ----------
__device__ __forceinline__ u64 dr_mufu2(u64 x) {
    const u64 K2PI  = pk2(TWO_PI_F, TWO_PI_F);
    const u64 KMI2P = pk2(-INV_TWO_PI_F, -INV_TWO_PI_F);
    u64 y = f2mul(x, K2PI);
    float ylo, yhi; upk2(y, ylo, yhi);
    u64 s = pk2(__sinf(ylo), __sinf(yhi));
    return f2fma(s, KMI2P, x);
}
__device__ __forceinline__ u64 hdr_mufu2(u64 x) { return dr_mufu2(dr_mufu2(dr_mufu2(x))); }

// ---------- packed dr via degree-9 Chebyshev poly (FMA pipe only) ----------
// u = x-0.5; dr(x) = x + u*G(u^2); G from Jacobi-Anger Chebyshev economization
// of sin(2*pi*u)/(2*pi) on |u|<=0.5; abs err ~1e-6.
__device__ __forceinline__ u64 dr_poly2(u64 x) {
    const u64 KMH = pk2(-0.5f, -0.5f);
    const u64 G4  = pk2( 5.2148544f,   5.2148544f);
    const u64 G3  = pk2(-11.8518504f, -11.8518504f);
    const u64 G2  = pk2( 12.9495198f,  12.9495198f);
    const u64 G1  = pk2(-6.5780281f,  -6.5780281f);
    const u64 G0  = pk2( 0.99997840f,  0.99997840f);
    u64 u = f2add(x, KMH);
    u64 e = f2mul(u, u);
    u64 p = f2fma(e, G4, G3);
    p = f2fma(p, e, G2);
    p = f2fma(p, e, G1);
    p = f2fma(p, e, G0);
    return f2fma(p, u, x);
}
__device__ __forceinline__ u64 hdr_poly2(u64 x) { return dr_poly2(dr_poly2(dr_poly2(x))); }

// full packed mask pair (m0,m1) for one pixel.
// eq-combine folded to single fma: t = a*(2b-1) + (1-b), with c1=2b-1, c0=1-b.
__device__ __forceinline__ u64 mask_pair(float4 v0, float4 v1,
                                         u64 c1_0, u64 c0_0, u64 c1_1, u64 c0_1,
                                         u64 c1_2, u64 c0_2, u64 c1_3, u64 c0_3) {
    u64 ah0 = hdr_poly2(pk2(v0.x, v1.x));
    u64 ah1 = hdr_poly2(pk2(v0.y, v1.y));
    u64 ah2 = hdr_poly2(pk2(v0.z, v1.z));
    u64 ah3 = hdr_poly2(pk2(v0.w, v1.w));

    u64 d0 = dr_mufu2(hdr_mufu2(f2fma(ah0, c1_0, c0_0)));
    u64 d1 = dr_mufu2(hdr_mufu2(f2fma(ah1, c1_1, c0_1)));
    u64 d2 = dr_mufu2(hdr_mufu2(f2fma(ah2, c1_2, c0_2)));
    u64 d3 = dr_mufu2(hdr_mufu2(f2fma(ah3, c1_3, c0_3)));

    u64 pa = f2mul(d0, d1);
    u64 pb = f2mul(d2, d3);
    // pipe balance: one final dr on poly (FMA), one on MUFU
    return f2mul(dr_poly2(pa), dr_mufu2(pb));
}

// One WARP per area: 32 threads x 8 pixels. No smem, no __syncthreads.
__global__ __launch_bounds__(256, 3)
void deconv_masks_kernel(const float*  __restrict__ img,
                         const float4* __restrict__ mask0,
                         const float4* __restrict__ mask1,
                         const float*  __restrict__ mid,
                         float*        __restrict__ out,
                         int n_pix_total, int n_areas)
{
    const int lane = threadIdx.x & 31;
    const int area = blockIdx.x * 8 + (threadIdx.x >> 5);
    if (area >= n_areas) return;

    // per-area id: lanes 0-3 load+hdr, broadcast to all lanes
    float h = 0.0f;
    if (lane < 4) h = hdr_s(mid[(size_t)area * 4 + lane]);
    const float h0 = __shfl_sync(0xffffffffu, h, 0);
    const float h1 = __shfl_sync(0xffffffffu, h, 1);
    const float h2 = __shfl_sync(0xffffffffu, h, 2);
    const float h3 = __shfl_sync(0xffffffffu, h, 3);

    const u64 c1_0 = pk2(2.0f*h0 - 1.0f, 2.0f*h0 - 1.0f), c0_0 = pk2(1.0f - h0, 1.0f - h0);
    const u64 c1_1 = pk2(2.0f*h1 - 1.0f, 2.0f*h1 - 1.0f), c0_1 = pk2(1.0f - h1, 1.0f - h1);
    const u64 c1_2 = pk2(2.0f*h2 - 1.0f, 2.0f*h2 - 1.0f), c0_2 = pk2(1.0f - h2, 1.0f - h2);
    const u64 c1_3 = pk2(2.0f*h3 - 1.0f, 2.0f*h3 - 1.0f), c0_3 = pk2(1.0f - h3, 1.0f - h3);

    const size_t base = (size_t)area * 256 + lane;

    float m0v[8], m1v[8];
    float4 acc = make_float4(0.f, 0.f, 0.f, 0.f);

    #pragma unroll
    for (int k = 0; k < 8; k++) {
        const size_t pix = base + (size_t)k * 32;
        const float  iv  = img[pix];
        const float4 v0  = mask0[pix];
        const float4 v1  = mask1[pix];
        u64 mm = mask_pair(v0, v1, c1_0, c0_0, c1_1, c0_1, c1_2, c0_2, c1_3, c0_3);
        float m0, m1; upk2(mm, m0, m1);
        m0v[k] = m0; m1v[k] = m1;
        acc.x = fmaf(m0, iv, acc.x);
        acc.y += m0;
        acc.z = fmaf(m1, iv, acc.z);
        acc.w += m1;
    }

    // warp-wide butterfly reduction (all lanes get totals)
    #pragma unroll
    for (int off = 16; off > 0; off >>= 1) {
        acc.x += __shfl_xor_sync(0xffffffffu, acc.x, off);
        acc.y += __shfl_xor_sync(0xffffffffu, acc.y, off);
        acc.z += __shfl_xor_sync(0xffffffffu, acc.z, off);
        acc.w += __shfl_xor_sync(0xffffffffu, acc.w, off);
    }

    const float mean0 = __fdividef(acc.x, acc.y);
    const float mean1 = __fdividef(acc.z, acc.w);

    #pragma unroll
    for (int k = 0; k < 8; k++) {
        const size_t pix = base + (size_t)k * 32;
        out[pix]                       = m0v[k] * mean0;
        out[pix + (size_t)n_pix_total] = m1v[k] * mean1;
    }
}

extern "C" void kernel_launch(void* const* d_in, const int* in_sizes, int n_in,
                              void* d_out, int out_size) {
    const float*  img   = (const float*) d_in[0];
    const float4* mask0 = (const float4*)d_in[1];
    const float4* mask1 = (const float4*)d_in[2];
    const float*  mid   = (const float*) d_in[3];
    float*        out   = (float*)d_out;

    const int n_pix  = in_sizes[0];     // B*N*256
    const int areas  = n_pix / 256;     // 16384
    const int blocks = (areas + 7) / 8;

    deconv_masks_kernel<<<blocks, 256>>>(img, mask0, mask1, mid, out, n_pix, areas);
}

// round 5
// speedup vs baseline: 1.4439x; 1.0412x over previous
#include <cuda_runtime.h>
#include <cuda_bf16.h>

#define TWO_PI_F     6.2831853071795864769f
#define INV_TWO_PI_F 0.15915494309189533577f
#define INV_4PI2_F   0.025330295910584444f   // 1/(4*pi^2)

typedef unsigned long long u64;

// ---------- packed f32x2 primitives (Blackwell) ----------
__device__ __forceinline__ u64 pk2(float lo, float hi) {
    u64 r; asm("mov.b64 %0, {%1,%2};" : "=l"(r) : "f"(lo), "f"(hi)); return r;
}
__device__ __forceinline__ void upk2(u64 v, float& lo, float& hi) {
    asm("mov.b64 {%0,%1}, %2;" : "=f"(lo), "=f"(hi) : "l"(v));
}
__device__ __forceinline__ u64 f2add(u64 a, u64 b) {
    u64 r; asm("add.rn.f32x2 %0,%1,%2;" : "=l"(r) : "l"(a), "l"(b)); return r;
}
__device__ __forceinline__ u64 f2mul(u64 a, u64 b) {
    u64 r; asm("mul.rn.f32x2 %0,%1,%2;" : "=l"(r) : "l"(a), "l"(b)); return r;
}
__device__ __forceinline__ u64 f2fma(u64 a, u64 b, u64 c) {
    u64 r; asm("fma.rn.f32x2 %0,%1,%2,%3;" : "=l"(r) : "l"(a), "l"(b), "l"(c)); return r;
}

// ---------- scalar dr (per-area id precompute only) ----------
__device__ __forceinline__ float dr_s(float x) {
    return fmaf(-__sinf(x * TWO_PI_F), INV_TWO_PI_F, x);
}
__device__ __forceinline__ float hdr_s(float x) { return dr_s(dr_s(dr_s(x))); }

// ---------- packed dr in PHASE SPACE: theta' = theta - sin(theta) ----------
// 2 MUFU + 1 FADD2; negation folds into ALU pipe.
__device__ __forceinline__ u64 dr_phase2(u64 ph) {
    float lo, hi; upk2(ph, lo, hi);
    u64 ns = pk2(-__sinf(lo), -__sinf(hi));
    return f2add(ph, ns);
}

// ---------- packed dr via degree-9 Chebyshev poly (FMA pipe, x-space) ----------
// u = x-0.5; dr(x) = x + u*G(u^2); abs err ~1e-6 on [0,1].
__device__ __forceinline__ u64 dr_poly2(u64 x) {
    const u64 KMH = pk2(-0.5f, -0.5f);
    const u64 G4  = pk2( 5.2148544f,   5.2148544f);
    const u64 G3  = pk2(-11.8518504f, -11.8518504f);
    const u64 G2  = pk2( 12.9495198f,  12.9495198f);
    const u64 G1  = pk2(-6.5780281f,  -6.5780281f);
    const u64 G0  = pk2( 0.99997840f,  0.99997840f);
    u64 u = f2add(x, KMH);
    u64 e = f2mul(u, u);
    u64 p = f2fma(e, G4, G3);
    p = f2fma(p, e, G2);
    p = f2fma(p, e, G1);
    p = f2fma(p, e, G0);
    return f2fma(p, u, x);
}
__device__ __forceinline__ u64 hdr_poly2(u64 x) { return dr_poly2(dr_poly2(dr_poly2(x))); }

// full packed mask pair for one pixel, output scaled by 4*pi^2:
//   mt = (2pi*dr(pa)) * (2pi*dr(pb))
// c1 = 2pi*(2h-1), c0 = 2pi*(1-h) fold the phase conversion into the eq-fma.
__device__ __forceinline__ u64 mask_pair_scaled(float4 v0, float4 v1,
                                                u64 c1_0, u64 c0_0, u64 c1_1, u64 c0_1,
                                                u64 c1_2, u64 c0_2, u64 c1_3, u64 c0_3,
                                                u64 KI2P) {
    // hdr(a): FMA pipe, x-space
    u64 ah0 = hdr_poly2(pk2(v0.x, v1.x));
    u64 ah1 = hdr_poly2(pk2(v0.y, v1.y));
    u64 ah2 = hdr_poly2(pk2(v0.z, v1.z));
    u64 ah3 = hdr_poly2(pk2(v0.w, v1.w));

    // phi_t = 2pi * (a*(2b-1) + (1-b)); then 4 phase-drs -> phi4 = 2pi*dr(hdr(t))
    u64 f0 = f2fma(ah0, c1_0, c0_0);
    u64 f1 = f2fma(ah1, c1_1, c0_1);
    u64 f2 = f2fma(ah2, c1_2, c0_2);
    u64 f3 = f2fma(ah3, c1_3, c0_3);

    #pragma unroll
    for (int i = 0; i < 4; i++) {
        f0 = dr_phase2(f0);
        f1 = dr_phase2(f1);
        f2 = dr_phase2(f2);
        f3 = dr_phase2(f3);
    }

    // phi_pa = 2pi*(d0*d1) = (phi4_0*phi4_1)/(2pi); same for pb
    u64 ppa = f2mul(f2mul(f0, f1), KI2P);
    u64 ppb = f2mul(f2mul(f2, f3), KI2P);

    // mt = (ppa - sin ppa)*(ppb - sin ppb) = 4pi^2 * m
    return f2mul(dr_phase2(ppa), dr_phase2(ppb));
}

// One WARP per area: 32 threads x 8 pixels. No smem, no __syncthreads.
__global__ __launch_bounds__(256, 3)
void deconv_masks_kernel(const float*  __restrict__ img,
                         const float4* __restrict__ mask0,
                         const float4* __restrict__ mask1,
                         const float*  __restrict__ mid,
                         float*        __restrict__ out,
                         int n_pix_total, int n_areas)
{
    const int lane = threadIdx.x & 31;
    const int area = blockIdx.x * 8 + (threadIdx.x >> 5);
    if (area >= n_areas) return;

    // per-area id: lanes 0-3 load+hdr, broadcast
    float h = 0.0f;
    if (lane < 4) h = hdr_s(mid[(size_t)area * 4 + lane]);
    const float h0 = __shfl_sync(0xffffffffu, h, 0);
    const float h1 = __shfl_sync(0xffffffffu, h, 1);
    const float h2 = __shfl_sync(0xffffffffu, h, 2);
    const float h3 = __shfl_sync(0xffffffffu, h, 3);

    // phase-folded eq constants: c1 = 2pi*(2h-1), c0 = 2pi*(1-h)
    #define MKC1(hh) pk2(TWO_PI_F*(2.0f*(hh)-1.0f), TWO_PI_F*(2.0f*(hh)-1.0f))
    #define MKC0(hh) pk2(TWO_PI_F*(1.0f-(hh)),      TWO_PI_F*(1.0f-(hh)))
    const u64 c1_0 = MKC1(h0), c0_0 = MKC0(h0);
    const u64 c1_1 = MKC1(h1), c0_1 = MKC0(h1);
    const u64 c1_2 = MKC1(h2), c0_2 = MKC0(h2);
    const u64 c1_3 = MKC1(h3), c0_3 = MKC0(h3);
    #undef MKC1
    #undef MKC0
    const u64 KI2P = pk2(INV_TWO_PI_F, INV_TWO_PI_F);

    const size_t base = (size_t)area * 256 + lane;

    float m0v[8], m1v[8];   // scaled by 4pi^2 (scale folded into mean at the end)
    float4 acc = make_float4(0.f, 0.f, 0.f, 0.f);

    #pragma unroll
    for (int k = 0; k < 8; k++) {
        const size_t pix = base + (size_t)k * 32;
        const float  iv  = img[pix];
        const float4 v0  = mask0[pix];
        const float4 v1  = mask1[pix];
        u64 mt = mask_pair_scaled(v0, v1, c1_0, c0_0, c1_1, c0_1,
                                  c1_2, c0_2, c1_3, c0_3, KI2P);
        float m0, m1; upk2(mt, m0, m1);
        m0v[k] = m0; m1v[k] = m1;
        acc.x = fmaf(m0, iv, acc.x);
        acc.y += m0;
        acc.z = fmaf(m1, iv, acc.z);
        acc.w += m1;
    }

    // warp-wide butterfly reduction
    #pragma unroll
    for (int off = 16; off > 0; off >>= 1) {
        acc.x += __shfl_xor_sync(0xffffffffu, acc.x, off);
        acc.y += __shfl_xor_sync(0xffffffffu, acc.y, off);
        acc.z += __shfl_xor_sync(0xffffffffu, acc.z, off);
        acc.w += __shfl_xor_sync(0xffffffffu, acc.w, off);
    }

    // mean picks up the 1/(4pi^2) un-scaling exactly once
    const float mean0 = __fdividef(acc.x, acc.y) * INV_4PI2_F;
    const float mean1 = __fdividef(acc.z, acc.w) * INV_4PI2_F;

    #pragma unroll
    for (int k = 0; k < 8; k++) {
        const size_t pix = base + (size_t)k * 32;
        out[pix]                       = m0v[k] * mean0;
        out[pix + (size_t)n_pix_total] = m1v[k] * mean1;
    }
}

extern "C" void kernel_launch(void* const* d_in, const int* in_sizes, int n_in,
                              void* d_out, int out_size) {
    const float*  img   = (const float*) d_in[0];
    const float4* mask0 = (const float4*)d_in[1];
    const float4* mask1 = (const float4*)d_in[2];
    const float*  mid   = (const float*) d_in[3];
    float*        out   = (float*)d_out;

    const int n_pix  = in_sizes[0];     // B*N*256
    const int areas  = n_pix / 256;     // 16384
    const int blocks = (areas + 7) / 8;

    deconv_masks_kernel<<<blocks, 256>>>(img, mask0, mask1, mid, out, n_pix, areas);
}

// round 6
// speedup vs baseline: 1.4449x; 1.0006x over previous
#include <cuda_runtime.h>
#include <cuda_bf16.h>

#define TWO_PI_F     6.2831853071795864769f
#define INV_TWO_PI_F 0.15915494309189533577f
#define INV_4PI2_F   0.025330295910584444f   // 1/(4*pi^2)

typedef unsigned long long u64;

// ---------- packed f32x2 primitives (Blackwell) ----------
__device__ __forceinline__ u64 pk2(float lo, float hi) {
    u64 r; asm("mov.b64 %0, {%1,%2};" : "=l"(r) : "f"(lo), "f"(hi)); return r;
}
__device__ __forceinline__ u64 pk2b(float v) {            // broadcast pack
    u64 r; asm("mov.b64 %0, {%1,%1};" : "=l"(r) : "f"(v)); return r;
}
__device__ __forceinline__ void upk2(u64 v, float& lo, float& hi) {
    asm("mov.b64 {%0,%1}, %2;" : "=f"(lo), "=f"(hi) : "l"(v));
}
__device__ __forceinline__ u64 f2add(u64 a, u64 b) {
    u64 r; asm("add.rn.f32x2 %0,%1,%2;" : "=l"(r) : "l"(a), "l"(b)); return r;
}
__device__ __forceinline__ u64 f2mul(u64 a, u64 b) {
    u64 r; asm("mul.rn.f32x2 %0,%1,%2;" : "=l"(r) : "l"(a), "l"(b)); return r;
}
__device__ __forceinline__ u64 f2fma(u64 a, u64 b, u64 c) {
    u64 r; asm("fma.rn.f32x2 %0,%1,%2,%3;" : "=l"(r) : "l"(a), "l"(b), "l"(c)); return r;
}

// ---------- scalar dr (per-area id precompute only) ----------
__device__ __forceinline__ float dr_s(float x) {
    return fmaf(-__sinf(x * TWO_PI_F), INV_TWO_PI_F, x);
}
__device__ __forceinline__ float hdr_s(float x) { return dr_s(dr_s(dr_s(x))); }

// ---------- packed dr in PHASE SPACE: theta' = theta - sin(theta) ----------
__device__ __forceinline__ u64 dr_phase2(u64 ph) {
    float lo, hi; upk2(ph, lo, hi);
    u64 ns = pk2(-__sinf(lo), -__sinf(hi));
    return f2add(ph, ns);
}

// ---------- packed dr via degree-9 Chebyshev poly (FMA pipe, x-space) ----------
__device__ __forceinline__ u64 dr_poly2(u64 x) {
    const u64 KMH = pk2b(-0.5f);
    const u64 G4  = pk2b( 5.2148544f);
    const u64 G3  = pk2b(-11.8518504f);
    const u64 G2  = pk2b( 12.9495198f);
    const u64 G1  = pk2b(-6.5780281f);
    const u64 G0  = pk2b( 0.99997840f);
    u64 u = f2add(x, KMH);
    u64 e = f2mul(u, u);
    u64 p = f2fma(e, G4, G3);
    p = f2fma(p, e, G2);
    p = f2fma(p, e, G1);
    p = f2fma(p, e, G0);
    return f2fma(p, u, x);
}
__device__ __forceinline__ u64 hdr_poly2(u64 x) { return dr_poly2(dr_poly2(dr_poly2(x))); }

// full packed mask pair (m0,m1) for one pixel, UNSCALED (x-space output).
// c1 = 2pi*(2h-1), c0 = 2pi*(1-h) passed as scalar floats, packed at use.
__device__ __forceinline__ u64 mask_pair(float4 v0, float4 v1,
                                         float c1_0, float c0_0, float c1_1, float c0_1,
                                         float c1_2, float c0_2, float c1_3, float c0_3) {
    // hdr(a): FMA pipe, x-space
    u64 ah0 = hdr_poly2(pk2(v0.x, v1.x));
    u64 ah1 = hdr_poly2(pk2(v0.y, v1.y));
    u64 ah2 = hdr_poly2(pk2(v0.z, v1.z));
    u64 ah3 = hdr_poly2(pk2(v0.w, v1.w));

    // phi_t = 2pi*(a*(2b-1) + (1-b)); then 4 phase-drs per channel (MUFU)
    u64 f0 = f2fma(ah0, pk2b(c1_0), pk2b(c0_0));
    u64 f1 = f2fma(ah1, pk2b(c1_1), pk2b(c0_1));
    u64 f2v = f2fma(ah2, pk2b(c1_2), pk2b(c0_2));
    u64 f3 = f2fma(ah3, pk2b(c1_3), pk2b(c0_3));

    #pragma unroll
    for (int i = 0; i < 4; i++) {
        f0 = dr_phase2(f0);
        f1 = dr_phase2(f1);
        f2v = dr_phase2(f2v);
        f3 = dr_phase2(f3);
    }

    // back to x-space: pa = (f0*f1)/(4pi^2), pb likewise; final drs on FMA pipe
    const u64 KI4 = pk2b(INV_4PI2_F);
    u64 pa = f2mul(f2mul(f0, f1), KI4);
    u64 pb = f2mul(f2mul(f2v, f3), KI4);
    return f2mul(dr_poly2(pa), dr_poly2(pb));   // m, unscaled
}

// 2 warps per area, 4 pixels per thread. Block = 256 threads = 4 areas.
__global__ __launch_bounds__(256, 4)
void deconv_masks_kernel(const float*  __restrict__ img,
                         const float4* __restrict__ mask0,
                         const float4* __restrict__ mask1,
                         const float*  __restrict__ mid,
                         float*        __restrict__ out,
                         int n_pix_total, int n_areas)
{
    __shared__ float4 part[8];

    const int tid   = threadIdx.x;
    const int lane  = tid & 31;
    const int wid   = tid >> 5;          // 0..7
    const int half  = wid & 1;           // which 128-pixel half of the area
    const int area  = blockIdx.x * 4 + (wid >> 1);
    if (area >= n_areas) return;

    // per-area id: lanes 0-3 load+hdr, broadcast (both warps of the pair redo this)
    float h = 0.0f;
    if (lane < 4) h = hdr_s(mid[(size_t)area * 4 + lane]);
    const float h0 = __shfl_sync(0xffffffffu, h, 0);
    const float h1 = __shfl_sync(0xffffffffu, h, 1);
    const float h2 = __shfl_sync(0xffffffffu, h, 2);
    const float h3 = __shfl_sync(0xffffffffu, h, 3);

    // phase-folded eq constants (scalar; packed at use)
    const float c1_0 = TWO_PI_F * (2.0f*h0 - 1.0f), c0_0 = TWO_PI_F * (1.0f - h0);
    const float c1_1 = TWO_PI_F * (2.0f*h1 - 1.0f), c0_1 = TWO_PI_F * (1.0f - h1);
    const float c1_2 = TWO_PI_F * (2.0f*h2 - 1.0f), c0_2 = TWO_PI_F * (1.0f - h2);
    const float c1_3 = TWO_PI_F * (2.0f*h3 - 1.0f), c0_3 = TWO_PI_F * (1.0f - h3);

    const size_t base = (size_t)area * 256 + (size_t)half * 128 + lane;

    float m0v[4], m1v[4];
    float4 acc = make_float4(0.f, 0.f, 0.f, 0.f);

    #pragma unroll
    for (int k = 0; k < 4; k++) {
        const size_t pix = base + (size_t)k * 32;
        const float  iv  = img[pix];
        const float4 v0  = mask0[pix];
        const float4 v1  = mask1[pix];
        u64 mm = mask_pair(v0, v1, c1_0, c0_0, c1_1, c0_1, c1_2, c0_2, c1_3, c0_3);
        float m0, m1; upk2(mm, m0, m1);
        m0v[k] = m0; m1v[k] = m1;
        acc.x = fmaf(m0, iv, acc.x);
        acc.y += m0;
        acc.z = fmaf(m1, iv, acc.z);
        acc.w += m1;
    }

    // warp-wide butterfly (all lanes get this warp's total)
    #pragma unroll
    for (int off = 16; off > 0; off >>= 1) {
        acc.x += __shfl_xor_sync(0xffffffffu, acc.x, off);
        acc.y += __shfl_xor_sync(0xffffffffu, acc.y, off);
        acc.z += __shfl_xor_sync(0xffffffffu, acc.z, off);
        acc.w += __shfl_xor_sync(0xffffffffu, acc.w, off);
    }

    // combine with partner warp via smem
    if (lane == 0) part[wid] = acc;
    __syncthreads();
    const float4 o = part[wid ^ 1];

    const float mean0 = __fdividef(acc.x + o.x, acc.y + o.y);
    const float mean1 = __fdividef(acc.z + o.z, acc.w + o.w);

    #pragma unroll
    for (int k = 0; k < 4; k++) {
        const size_t pix = base + (size_t)k * 32;
        out[pix]                       = m0v[k] * mean0;
        out[pix + (size_t)n_pix_total] = m1v[k] * mean1;
    }
}

extern "C" void kernel_launch(void* const* d_in, const int* in_sizes, int n_in,
                              void* d_out, int out_size) {
    const float*  img   = (const float*) d_in[0];
    const float4* mask0 = (const float4*)d_in[1];
    const float4* mask1 = (const float4*)d_in[2];
    const float*  mid   = (const float*) d_in[3];
    float*        out   = (float*)d_out;

    const int n_pix  = in_sizes[0];     // B*N*256
    const int areas  = n_pix / 256;     // 16384
    const int blocks = (areas + 3) / 4;

    deconv_masks_kernel<<<blocks, 256>>>(img, mask0, mask1, mid, out, n_pix, areas);
}

// round 7
// speedup vs baseline: 1.4571x; 1.0085x over previous
#include <cuda_runtime.h>
#include <cuda_bf16.h>

#define TWO_PI_F     6.2831853071795864769f
#define INV_TWO_PI_F 0.15915494309189533577f
#define INV_4PI2_F   0.025330295910584444f   // 1/(4*pi^2)

typedef unsigned long long u64;

// ---------- packed f32x2 primitives (Blackwell) ----------
__device__ __forceinline__ u64 pk2(float lo, float hi) {
    u64 r; asm("mov.b64 %0, {%1,%2};" : "=l"(r) : "f"(lo), "f"(hi)); return r;
}
__device__ __forceinline__ u64 pk2b(float v) {
    u64 r; asm("mov.b64 %0, {%1,%1};" : "=l"(r) : "f"(v)); return r;
}
__device__ __forceinline__ void upk2(u64 v, float& lo, float& hi) {
    asm("mov.b64 {%0,%1}, %2;" : "=f"(lo), "=f"(hi) : "l"(v));
}
__device__ __forceinline__ u64 f2add(u64 a, u64 b) {
    u64 r; asm("add.rn.f32x2 %0,%1,%2;" : "=l"(r) : "l"(a), "l"(b)); return r;
}
__device__ __forceinline__ u64 f2mul(u64 a, u64 b) {
    u64 r; asm("mul.rn.f32x2 %0,%1,%2;" : "=l"(r) : "l"(a), "l"(b)); return r;
}
__device__ __forceinline__ u64 f2fma(u64 a, u64 b, u64 c) {
    u64 r; asm("fma.rn.f32x2 %0,%1,%2,%3;" : "=l"(r) : "l"(a), "l"(b), "l"(c)); return r;
}

// ---------- scalar dr (per-area id precompute only) ----------
__device__ __forceinline__ float dr_s(float x) {
    return fmaf(-__sinf(x * TWO_PI_F), INV_TWO_PI_F, x);
}
__device__ __forceinline__ float hdr_s(float x) { return dr_s(dr_s(dr_s(x))); }

// ---------- packed dr in PHASE SPACE: theta' = theta - sin(theta) (MUFU) ----------
__device__ __forceinline__ u64 dr_phase2(u64 ph) {
    float lo, hi; upk2(ph, lo, hi);
    u64 ns = pk2(-__sinf(lo), -__sinf(hi));
    return f2add(ph, ns);
}

// ---------- packed dr, degree-7 economized poly (FMA pipe, x-space) ----------
// u=x-0.5; dr(x)=x+u*G(u^2); economized from the verified deg-9 set; err<=~8e-5.
__device__ __forceinline__ u64 dr_poly7(u64 x) {
    const u64 KMH = pk2b(-0.5f);
    const u64 H3  = pk2b(-9.2444232f);
    const u64 H2  = pk2b( 12.5421093f);
    const u64 H1  = pk2b(-6.5576576f);
    const u64 H0  = pk2b( 0.99981925f);
    u64 u = f2add(x, KMH);
    u64 e = f2mul(u, u);
    u64 p = f2fma(e, H3, H2);
    p = f2fma(p, e, H1);
    p = f2fma(p, e, H0);
    return f2fma(p, u, x);
}
__device__ __forceinline__ u64 hdr_poly7(u64 x) { return dr_poly7(dr_poly7(dr_poly7(x))); }

// ---------- packed dr, degree-9 poly (final drs, higher accuracy) ----------
__device__ __forceinline__ u64 dr_poly9(u64 x) {
    const u64 KMH = pk2b(-0.5f);
    const u64 G4  = pk2b( 5.2148544f);
    const u64 G3  = pk2b(-11.8518504f);
    const u64 G2  = pk2b( 12.9495198f);
    const u64 G1  = pk2b(-6.5780281f);
    const u64 G0  = pk2b( 0.99997840f);
    u64 u = f2add(x, KMH);
    u64 e = f2mul(u, u);
    u64 p = f2fma(e, G4, G3);
    p = f2fma(p, e, G2);
    p = f2fma(p, e, G1);
    p = f2fma(p, e, G0);
    return f2fma(p, u, x);
}

// 2 warps per area, 4 pixels per thread, software-pipelined:
// pixel k+1's hdr(a) (FMA) is interleaved between pixel k's phase-dr rounds (MUFU).
__global__ __launch_bounds__(256, 3)
void deconv_masks_kernel(const float*  __restrict__ img,
                         const float4* __restrict__ mask0,
                         const float4* __restrict__ mask1,
                         const float*  __restrict__ mid,
                         float*        __restrict__ out,
                         int n_pix_total, int n_areas)
{
    __shared__ float4 part[8];

    const int tid   = threadIdx.x;
    const int lane  = tid & 31;
    const int wid   = tid >> 5;
    const int half  = wid & 1;
    const int area  = blockIdx.x * 4 + (wid >> 1);
    if (area >= n_areas) return;

    float h = 0.0f;
    if (lane < 4) h = hdr_s(mid[(size_t)area * 4 + lane]);
    const float h0 = __shfl_sync(0xffffffffu, h, 0);
    const float h1 = __shfl_sync(0xffffffffu, h, 1);
    const float h2 = __shfl_sync(0xffffffffu, h, 2);
    const float h3 = __shfl_sync(0xffffffffu, h, 3);

    // phase-folded eq constants: phi_t = ah*c1 + c0 = 2pi*t
    const u64 C1_0 = pk2b(TWO_PI_F*(2.0f*h0 - 1.0f)), C0_0 = pk2b(TWO_PI_F*(1.0f - h0));
    const u64 C1_1 = pk2b(TWO_PI_F*(2.0f*h1 - 1.0f)), C0_1 = pk2b(TWO_PI_F*(1.0f - h1));
    const u64 C1_2 = pk2b(TWO_PI_F*(2.0f*h2 - 1.0f)), C0_2 = pk2b(TWO_PI_F*(1.0f - h2));
    const u64 C1_3 = pk2b(TWO_PI_F*(2.0f*h3 - 1.0f)), C0_3 = pk2b(TWO_PI_F*(1.0f - h3));
    const u64 KI4  = pk2b(INV_4PI2_F);

    const size_t base = (size_t)area * 256 + (size_t)half * 128 + lane;

    float m0v[4], m1v[4];
    float4 acc = make_float4(0.f, 0.f, 0.f, 0.f);

    // ---- prologue: load + hdr(a) for k=0 ----
    float4 v0 = mask0[base];
    float4 v1 = mask1[base];
    float  iv = img[base];
    u64 ah0 = hdr_poly7(pk2(v0.x, v1.x));
    u64 ah1 = hdr_poly7(pk2(v0.y, v1.y));
    u64 ah2 = hdr_poly7(pk2(v0.z, v1.z));
    u64 ah3 = hdr_poly7(pk2(v0.w, v1.w));

    #pragma unroll
    for (int k = 0; k < 4; k++) {
        // issue next pixel's loads first (long latency)
        float4 w0, w1; float niv = 0.0f;
        if (k < 3) {
            const size_t np = base + (size_t)(k + 1) * 32;
            w0 = mask0[np];
            w1 = mask1[np];
            niv = img[np];
        }

        // eq: phi = 2pi*t, then phase-dr round 1 (MUFU)
        u64 f0 = f2fma(ah0, C1_0, C0_0);
        u64 f1 = f2fma(ah1, C1_1, C0_1);
        u64 f2v = f2fma(ah2, C1_2, C0_2);
        u64 f3 = f2fma(ah3, C1_3, C0_3);
        f0 = dr_phase2(f0);  f1 = dr_phase2(f1);
        f2v = dr_phase2(f2v); f3 = dr_phase2(f3);

        // interleave FMA work: next pixel's hdr(a), channels 0-1
        u64 nah0 = 0, nah1 = 0, nah2 = 0, nah3 = 0;
        if (k < 3) {
            nah0 = hdr_poly7(pk2(w0.x, w1.x));
            nah1 = hdr_poly7(pk2(w0.y, w1.y));
        }

        // phase-dr round 2 (MUFU)
        f0 = dr_phase2(f0);  f1 = dr_phase2(f1);
        f2v = dr_phase2(f2v); f3 = dr_phase2(f3);

        // interleave FMA work: next pixel's hdr(a), channels 2-3
        if (k < 3) {
            nah2 = hdr_poly7(pk2(w0.z, w1.z));
            nah3 = hdr_poly7(pk2(w0.w, w1.w));
        }

        // phase-dr rounds 3 and 4 (MUFU)
        f0 = dr_phase2(f0);  f1 = dr_phase2(f1);
        f2v = dr_phase2(f2v); f3 = dr_phase2(f3);
        f0 = dr_phase2(f0);  f1 = dr_phase2(f1);
        f2v = dr_phase2(f2v); f3 = dr_phase2(f3);

        // back to x-space, final drs on FMA pipe
        u64 pa = f2mul(f2mul(f0, f1), KI4);
        u64 pb = f2mul(f2mul(f2v, f3), KI4);
        u64 mm = f2mul(dr_poly9(pa), dr_poly9(pb));

        float m0, m1; upk2(mm, m0, m1);
        m0v[k] = m0; m1v[k] = m1;
        acc.x = fmaf(m0, iv, acc.x);
        acc.y += m0;
        acc.z = fmaf(m1, iv, acc.z);
        acc.w += m1;

        // rotate pipeline
        ah0 = nah0; ah1 = nah1; ah2 = nah2; ah3 = nah3;
        iv = niv;
    }

    // warp-wide butterfly
    #pragma unroll
    for (int off = 16; off > 0; off >>= 1) {
        acc.x += __shfl_xor_sync(0xffffffffu, acc.x, off);
        acc.y += __shfl_xor_sync(0xffffffffu, acc.y, off);
        acc.z += __shfl_xor_sync(0xffffffffu, acc.z, off);
        acc.w += __shfl_xor_sync(0xffffffffu, acc.w, off);
    }

    if (lane == 0) part[wid] = acc;
    __syncthreads();
    const float4 o = part[wid ^ 1];

    const float mean0 = __fdividef(acc.x + o.x, acc.y + o.y);
    const float mean1 = __fdividef(acc.z + o.z, acc.w + o.w);

    #pragma unroll
    for (int k = 0; k < 4; k++) {
        const size_t pix = base + (size_t)k * 32;
        out[pix]                       = m0v[k] * mean0;
        out[pix + (size_t)n_pix_total] = m1v[k] * mean1;
    }
}

extern "C" void kernel_launch(void* const* d_in, const int* in_sizes, int n_in,
                              void* d_out, int out_size) {
    const float*  img   = (const float*) d_in[0];
    const float4* mask0 = (const float4*)d_in[1];
    const float4* mask1 = (const float4*)d_in[2];
    const float*  mid   = (const float*) d_in[3];
    float*        out   = (float*)d_out;

    const int n_pix  = in_sizes[0];
    const int areas  = n_pix / 256;
    const int blocks = (areas + 3) / 4;

    deconv_masks_kernel<<<blocks, 256>>>(img, mask0, mask1, mid, out, n_pix, areas);
}

// round 9
// speedup vs baseline: 1.5071x; 1.0343x over previous
#include <cuda_runtime.h>
#include <cuda_bf16.h>

#define TWO_PI_F     6.2831853071795864769f
#define PI_F         3.14159265358979323846f
#define INV_TWO_PI_F 0.15915494309189533577f
#define INV_4PI2_F   0.025330295910584444f   // 1/(4*pi^2)

typedef unsigned long long u64;

// ---------- packed f32x2 primitives (Blackwell) ----------
__device__ __forceinline__ u64 pk2(float lo, float hi) {
    u64 r; asm("mov.b64 %0, {%1,%2};" : "=l"(r) : "f"(lo), "f"(hi)); return r;
}
__device__ __forceinline__ u64 pk2b(float v) {
    u64 r; asm("mov.b64 %0, {%1,%1};" : "=l"(r) : "f"(v)); return r;
}
__device__ __forceinline__ void upk2(u64 v, float& lo, float& hi) {
    asm("mov.b64 {%0,%1}, %2;" : "=f"(lo), "=f"(hi) : "l"(v));
}
__device__ __forceinline__ u64 f2add(u64 a, u64 b) {
    u64 r; asm("add.rn.f32x2 %0,%1,%2;" : "=l"(r) : "l"(a), "l"(b)); return r;
}
__device__ __forceinline__ u64 f2mul(u64 a, u64 b) {
    u64 r; asm("mul.rn.f32x2 %0,%1,%2;" : "=l"(r) : "l"(a), "l"(b)); return r;
}
__device__ __forceinline__ u64 f2fma(u64 a, u64 b, u64 c) {
    u64 r; asm("fma.rn.f32x2 %0,%1,%2,%3;" : "=l"(r) : "l"(a), "l"(b), "l"(c)); return r;
}

// ---------- scalar dr (per-area id precompute only) ----------
__device__ __forceinline__ float dr_s(float x) {
    return fmaf(-__sinf(x * TWO_PI_F), INV_TWO_PI_F, x);
}
__device__ __forceinline__ float hdr_s(float x) { return dr_s(dr_s(dr_s(x))); }

// ---------- packed dr in PHASE SPACE: theta' = theta - sin(theta) (MUFU) ----------
__device__ __forceinline__ u64 dr_phase2(u64 ph) {
    float lo, hi; upk2(ph, lo, hi);
    u64 ns = pk2(-__sinf(lo), -__sinf(hi));
    return f2add(ph, ns);
}

// ---------- packed dr, degree-7 economized poly (FMA pipe, x-space) ----------
// VERIFIED accuracy in R7 (rel_err 1.4e-5 end-to-end).
__device__ __forceinline__ u64 dr_poly7(u64 x) {
    const u64 KMH = pk2b(-0.5f);
    const u64 H3  = pk2b(-9.2444232f);
    const u64 H2  = pk2b( 12.5421093f);
    const u64 H1  = pk2b(-6.5576576f);
    const u64 H0  = pk2b( 0.99981925f);
    u64 u = f2add(x, KMH);
    u64 e = f2mul(u, u);
    u64 p = f2fma(e, H3, H2);
    p = f2fma(p, e, H1);
    p = f2fma(p, e, H0);
    return f2fma(p, u, x);
}
__device__ __forceinline__ u64 hdr_poly7(u64 x) { return dr_poly7(dr_poly7(dr_poly7(x))); }

// ---------- packed dr, degree-7, PHASE-SCALED OUTPUT: phi = 2*pi*dr(x) ----------
// phi = pi + u * (2*pi*(1 + H(u^2))). Same deg-7 accuracy as dr_poly7.
__device__ __forceinline__ u64 dr_poly7_phase(u64 x) {
    const u64 KMH = pk2b(-0.5f);
    const u64 B3  = pk2b(-58.08440f);
    const u64 B2  = pk2b( 78.80440f);
    const u64 B1  = pk2b(-41.20490f);
    const u64 B0  = pk2b( 12.565245f);
    const u64 KPI = pk2b(PI_F);
    u64 u = f2add(x, KMH);
    u64 e = f2mul(u, u);
    u64 p = f2fma(e, B3, B2);
    p = f2fma(p, e, B1);
    p = f2fma(p, e, B0);
    return f2fma(p, u, KPI);
}

// ---------- packed dr, degree-9 (final drs, high accuracy, x-space) ----------
__device__ __forceinline__ u64 dr_poly9(u64 x) {
    const u64 KMH = pk2b(-0.5f);
    const u64 G4  = pk2b( 5.2148544f);
    const u64 G3  = pk2b(-11.8518504f);
    const u64 G2  = pk2b( 12.9495198f);
    const u64 G1  = pk2b(-6.5780281f);
    const u64 G0  = pk2b( 0.99997840f);
    u64 u = f2add(x, KMH);
    u64 e = f2mul(u, u);
    u64 p = f2fma(e, G4, G3);
    p = f2fma(p, e, G2);
    p = f2fma(p, e, G1);
    p = f2fma(p, e, G0);
    return f2fma(p, u, x);
}

// 2 warps per area, 4 pixels per thread.
// Channels 0,1: eq->phase, 4 MUFU phase-drs.
// Channels 2,3: eq->x, poly phase-dr (FMA), then 3 MUFU phase-drs.
__global__ __launch_bounds__(256, 3)
void deconv_masks_kernel(const float*  __restrict__ img,
                         const float4* __restrict__ mask0,
                         const float4* __restrict__ mask1,
                         const float*  __restrict__ mid,
                         float*        __restrict__ out,
                         int n_pix_total, int n_areas)
{
    __shared__ float4 part[8];

    const int tid   = threadIdx.x;
    const int lane  = tid & 31;
    const int wid   = tid >> 5;
    const int half  = wid & 1;
    const int area  = blockIdx.x * 4 + (wid >> 1);
    if (area >= n_areas) return;

    float h = 0.0f;
    if (lane < 4) h = hdr_s(mid[(size_t)area * 4 + lane]);
    const float h0 = __shfl_sync(0xffffffffu, h, 0);
    const float h1 = __shfl_sync(0xffffffffu, h, 1);
    const float h2 = __shfl_sync(0xffffffffu, h, 2);
    const float h3 = __shfl_sync(0xffffffffu, h, 3);

    // ch 0,1: phase-folded eq consts (phi_t = ah*c1 + c0 = 2pi*t)
    const u64 C1_0 = pk2b(TWO_PI_F*(2.0f*h0 - 1.0f)), C0_0 = pk2b(TWO_PI_F*(1.0f - h0));
    const u64 C1_1 = pk2b(TWO_PI_F*(2.0f*h1 - 1.0f)), C0_1 = pk2b(TWO_PI_F*(1.0f - h1));
    // ch 2,3: x-space eq consts (t = ah*(2h-1) + (1-h))
    const u64 D1_2 = pk2b(2.0f*h2 - 1.0f), D0_2 = pk2b(1.0f - h2);
    const u64 D1_3 = pk2b(2.0f*h3 - 1.0f), D0_3 = pk2b(1.0f - h3);
    const u64 KI4  = pk2b(INV_4PI2_F);

    const size_t base = (size_t)area * 256 + (size_t)half * 128 + lane;

    u64 mv[4];
    float4 acc = make_float4(0.f, 0.f, 0.f, 0.f);

    // prefetch pixel 0
    float4 v0 = mask0[base];
    float4 v1 = mask1[base];
    float  iv = img[base];

    #pragma unroll
    for (int k = 0; k < 4; k++) {
        // issue next pixel's loads early
        float4 w0, w1; float niv = 0.0f;
        if (k < 3) {
            const size_t np = base + (size_t)(k + 1) * 32;
            w0 = mask0[np]; w1 = mask1[np]; niv = img[np];
        }

        // hdr(a): deg-7 polys (FMA) — verified accuracy
        u64 ah0 = hdr_poly7(pk2(v0.x, v1.x));
        u64 ah1 = hdr_poly7(pk2(v0.y, v1.y));
        u64 ah2 = hdr_poly7(pk2(v0.z, v1.z));
        u64 ah3 = hdr_poly7(pk2(v0.w, v1.w));

        // ch 0,1: straight to phase, 4 MUFU rounds
        u64 f0 = f2fma(ah0, C1_0, C0_0);
        u64 f1 = f2fma(ah1, C1_1, C0_1);
        // ch 2,3: x-space eq, then poly phase-dr (round 1 on FMA)
        u64 f2v = dr_poly7_phase(f2fma(ah2, D1_2, D0_2));
        u64 f3  = dr_poly7_phase(f2fma(ah3, D1_3, D0_3));

        f0 = dr_phase2(f0); f1 = dr_phase2(f1);            // ch01 round 1
        f0 = dr_phase2(f0); f1 = dr_phase2(f1);            // ch01 round 2
        f2v = dr_phase2(f2v); f3 = dr_phase2(f3);          // ch23 round 2
        f0 = dr_phase2(f0); f1 = dr_phase2(f1);            // ch01 round 3
        f2v = dr_phase2(f2v); f3 = dr_phase2(f3);          // ch23 round 3
        f0 = dr_phase2(f0); f1 = dr_phase2(f1);            // ch01 round 4
        f2v = dr_phase2(f2v); f3 = dr_phase2(f3);          // ch23 round 4

        // back to x-space; final drs on FMA pipe
        u64 pa = f2mul(f2mul(f0, f1), KI4);
        u64 pb = f2mul(f2mul(f2v, f3), KI4);
        u64 mm = f2mul(dr_poly9(pa), dr_poly9(pb));

        mv[k] = mm;
        float m0, m1; upk2(mm, m0, m1);
        acc.x = fmaf(m0, iv, acc.x);
        acc.y += m0;
        acc.z = fmaf(m1, iv, acc.z);
        acc.w += m1;

        v0 = w0; v1 = w1; iv = niv;
    }

    // warp-wide butterfly
    #pragma unroll
    for (int off = 16; off > 0; off >>= 1) {
        acc.x += __shfl_xor_sync(0xffffffffu, acc.x, off);
        acc.y += __shfl_xor_sync(0xffffffffu, acc.y, off);
        acc.z += __shfl_xor_sync(0xffffffffu, acc.z, off);
        acc.w += __shfl_xor_sync(0xffffffffu, acc.w, off);
    }

    if (lane == 0) part[wid] = acc;
    __syncthreads();
    const float4 o = part[wid ^ 1];

    const float mean0 = __fdividef(acc.x + o.x, acc.y + o.y);
    const float mean1 = __fdividef(acc.z + o.z, acc.w + o.w);
    const u64 KMEAN = pk2(mean0, mean1);

    #pragma unroll
    for (int k = 0; k < 4; k++) {
        const size_t pix = base + (size_t)k * 32;
        u64 ow = f2mul(mv[k], KMEAN);
        float o0, o1; upk2(ow, o0, o1);
        out[pix]                       = o0;
        out[pix + (size_t)n_pix_total] = o1;
    }
}

extern "C" void kernel_launch(void* const* d_in, const int* in_sizes, int n_in,
                              void* d_out, int out_size) {
    const float*  img   = (const float*) d_in[0];
    const float4* mask0 = (const float4*)d_in[1];
    const float4* mask1 = (const float4*)d_in[2];
    const float*  mid   = (const float*) d_in[3];
    float*        out   = (float*)d_out;

    const int n_pix  = in_sizes[0];
    const int areas  = n_pix / 256;
    const int blocks = (areas + 3) / 4;

    deconv_masks_kernel<<<blocks, 256>>>(img, mask0, mask1, mid, out, n_pix, areas);
}